// round 8
// baseline (speedup 1.0000x reference)
#include <cuda_runtime.h>
#include <cstdint>

// PolyLoss: N=4096 rows, V=128 circular shifts, last dim = 2 (packed f32x2).
// per_shift[n,s] = (1/V) sum_v |pred[n,(s+v)%V] - gt[n,v]|_1 ; loss = mean_n min_s
//
// R3 shape (best measured occ/issue) + lean stream:
// 2 rows per 128-thread CTA, 2 warps per row (warp half h covers v in
// [64h,64h+64)). Lane owns shifts 4*lane..4*lane+3. Mainloop FULLY unrolled
// with fresh per-iter loads -> ptxas CSEs overlapping window loads, renames
// slides away, schedules LDS ahead. launch_bounds(128,12) caps regs at 42
// -> 12 CTAs/SM = 48 warps resident.

#define NROWS 4096
#define V 128
#define NCTA 2048            // 2 rows per CTA, 4 warps
#define THREADS 128

__device__ float g_partial[NCTA];
__device__ int g_ctr;

__device__ __forceinline__ uint64_t fma2(uint64_t a, uint64_t b, uint64_t c) {
    uint64_t d;
    asm("fma.rn.f32x2 %0, %1, %2, %3;" : "=l"(d) : "l"(a), "l"(b), "l"(c));
    return d;
}

// acc += | p - g | (componentwise, packed): FFMA2 + 2xLOP3 + FFMA2
#define ACC(p2, g2, acc) do {                      \
    uint64_t _d = fma2((g2), NEG1, (p2));          \
    _d &= 0x7fffffff7fffffffULL;                   \
    (acc) = fma2(_d, ONE1, (acc));                 \
} while (0)

__global__ void __launch_bounds__(THREADS, 12) polyloss_kernel(
    const float* __restrict__ pred, const float* __restrict__ gt,
    float* __restrict__ out)
{
    // Entry e_k = ulonglong2 = positions (2k, 2k+1), k=0..63 circular.
    // Even entries in sA, odd in sB (e_{2j}=sA[j], e_{2j+1}=sB[j]), both
    // duplicated (sX[j]=sX[j+32]) so window index boff+m+1 <= 64 never wraps.
    __shared__ ulonglong2 sA[2][66];
    __shared__ ulonglong2 sB[2][66];
    __shared__ ulonglong2 sg[2][64];
    __shared__ float4 ssum[4][32];
    __shared__ float s_rowmin[2];
    __shared__ int s_is_last;
    __shared__ float s_red[THREADS];

    const int tid  = threadIdx.x;
    const int w    = tid >> 5;
    const int lane = tid & 31;
    const int rl   = w >> 1;     // row within CTA (0,1)
    const int half = w & 1;      // v-half this warp covers

    const uint64_t NEG1 = 0xBF800000BF800000ULL;
    const uint64_t ONE1 = 0x3F8000003F800000ULL;

    // ---- stage 2 rows with 64 threads each ----
    {
        const int rr = tid >> 6;         // staging row
        const int i  = tid & 63;         // entry index
        const ulonglong2* prow =
            reinterpret_cast<const ulonglong2*>(pred) + (blockIdx.x * 2 + rr) * 64;
        const ulonglong2* grow =
            reinterpret_cast<const ulonglong2*>(gt)   + (blockIdx.x * 2 + rr) * 64;
        ulonglong2 r = prow[i];
        const int j = i >> 1;
        if (i & 1) { sB[rr][j] = r; sB[rr][j + 32] = r; }
        else       { sA[rr][j] = r; sA[rr][j + 32] = r; }
        if (i < 4) {   // e_{64+i} = e_i  (pad entries 64,65)
            if (i & 1) sB[rr][64 + (i >> 1)] = r;
            else       sA[rr][64 + (i >> 1)] = r;
        }
        sg[rr][i] = grow[i];
    }
    __syncthreads();

    // ---- mainloop: FULLY unrolled 16 blocks x 4 v's ----
    // Thread owns shifts 4*lane..4*lane+3. Block m covers v-offsets 4m..4m+3
    // within this warp's half; window = positions 4*(boff+m) .. +7, i.e.
    // entries A[boff+m], B[boff+m], A[boff+m+1], B[boff+m+1].
    uint64_t a0 = 0, a1 = 0, a2 = 0, a3 = 0;
    const int boff = lane + 16 * half;
    const ulonglong2* Ap = sA[rl];
    const ulonglong2* Bp = sB[rl];
    const ulonglong2* gp = sg[rl] + 32 * half;

    #pragma unroll
    for (int m = 0; m < 16; m++) {
        ulonglong2 G0 = gp[2 * m];        // gt[v0], gt[v0+1]   (broadcast)
        ulonglong2 G1 = gp[2 * m + 1];    // gt[v0+2], gt[v0+3] (broadcast)
        ulonglong2 Fa = Ap[boff + m];     // positions r+0, r+1
        ulonglong2 Fb = Bp[boff + m];     // r+2, r+3
        ulonglong2 Fc = Ap[boff + m + 1]; // r+4, r+5  (CSE with next iter's Fa)
        ulonglong2 Fd = Bp[boff + m + 1]; // r+6, r+7  (CSE with next iter's Fb)
        // u=0: positions r+0..r+3 for shifts 0..3
        ACC(Fa.x, G0.x, a0); ACC(Fa.y, G0.x, a1); ACC(Fb.x, G0.x, a2); ACC(Fb.y, G0.x, a3);
        // u=1
        ACC(Fa.y, G0.y, a0); ACC(Fb.x, G0.y, a1); ACC(Fb.y, G0.y, a2); ACC(Fc.x, G0.y, a3);
        // u=2
        ACC(Fb.x, G1.x, a0); ACC(Fb.y, G1.x, a1); ACC(Fc.x, G1.x, a2); ACC(Fc.y, G1.x, a3);
        // u=3
        ACC(Fb.y, G1.y, a0); ACC(Fc.x, G1.y, a1); ACC(Fc.y, G1.y, a2); ACC(Fd.x, G1.y, a3);
    }

    // ---- per-(thread,shift) partials -> smem ----
    float s0 = __uint_as_float((uint32_t)a0) + __uint_as_float((uint32_t)(a0 >> 32));
    float s1 = __uint_as_float((uint32_t)a1) + __uint_as_float((uint32_t)(a1 >> 32));
    float s2 = __uint_as_float((uint32_t)a2) + __uint_as_float((uint32_t)(a2 >> 32));
    float s3 = __uint_as_float((uint32_t)a3) + __uint_as_float((uint32_t)(a3 >> 32));
    ssum[w][lane] = make_float4(s0, s1, s2, s3);
    __syncthreads();

    // ---- combine v-halves, row min (warps 0,1 each handle one row) ----
    if (w < 2) {
        float4 x = ssum[2 * w][lane];
        float4 y = ssum[2 * w + 1][lane];
        float t0 = x.x + y.x, t1 = x.y + y.y, t2 = x.z + y.z, t3 = x.w + y.w;
        float mn = fminf(fminf(t0, t1), fminf(t2, t3));
        #pragma unroll
        for (int off = 16; off > 0; off >>= 1)
            mn = fminf(mn, __shfl_xor_sync(0xffffffffu, mn, off));
        if (lane == 0) s_rowmin[w] = mn;
    }
    __syncthreads();

    // ---- CTA partial + last-CTA ticket reduction ----
    if (tid == 0) {
        g_partial[blockIdx.x] = s_rowmin[0] + s_rowmin[1];
        __threadfence();
        int ticket = atomicAdd(&g_ctr, 1);
        s_is_last = (ticket == NCTA - 1);
    }
    __syncthreads();

    if (s_is_last) {
        __threadfence();
        float acc = 0.f;
        #pragma unroll
        for (int i = tid; i < NCTA; i += THREADS)
            acc += g_partial[i];
        s_red[tid] = acc;
        __syncthreads();
        #pragma unroll
        for (int off = THREADS / 2; off > 0; off >>= 1) {
            if (tid < off) s_red[tid] += s_red[tid + off];
            __syncthreads();
        }
        if (tid == 0) {
            out[0] = s_red[0] * (1.0f / ((float)NROWS * (float)V));
            g_ctr = 0;  // reset for next graph replay
        }
    }
}

extern "C" void kernel_launch(void* const* d_in, const int* in_sizes, int n_in,
                              void* d_out, int out_size)
{
    const float* pred = (const float*)d_in[0];
    const float* gt   = (const float*)d_in[1];
    polyloss_kernel<<<NCTA, THREADS>>>(pred, gt, (float*)d_out);
}

// round 11
// speedup vs baseline: 1.0864x; 1.0864x over previous
#include <cuda_runtime.h>
#include <cstdint>

// PolyLoss: N=4096 rows, V=128 circular shifts, last dim = 2.
// per_shift[n,s] = (1/V) sum_v |pred[n,(s+v)%V] - gt[n,v]|_1 ; loss = mean_n min_s
//
// Identity: |a-b| = a + b - 2*min(a,b); sum_v (p_{(s+v)%V} + g_v) = P + G is
// shift-invariant. So  min_s per_shift = ( (P+G) - 2 * max_s sum_v min(p,g) ) / V.
// Inner loop per (shift,v) pair: 2x FMNMX (alu pipe) + 2x FADD (fma pipe)
// = 4+4 pipe cycles, vs 8 fma + 4 alu for the |.| formulation.
// (min.f32x2 does not exist in PTX -- scalar FMNMX is the legal encoding.)
//
// Shape: 2 rows per 128-thread CTA, 2 warps/row (warp half h covers v in
// [64h,64h+64)), lane owns shifts 4*lane..4*lane+3, mainloop fully unrolled
// with CSE'd float4 window loads.

#define NROWS 4096
#define V 128
#define NCTA 2048
#define THREADS 128

__device__ float g_partial[NCTA];
__device__ int g_ctr;

// accx += min(px,gx); accy += min(py,gy)   (FMNMX + FADD per component)
#define ACC(P, QX, QY, G, ax, ay) do {       \
    (ax) += fminf((P).QX, (G).x);            \
    (ay) += fminf((P).QY, (G).y);            \
} while (0)

__global__ void __launch_bounds__(THREADS, 12) polyloss_kernel(
    const float* __restrict__ pred, const float* __restrict__ gt,
    float* __restrict__ out)
{
    // Entry e_k = float4 = positions (2k, 2k+1), k=0..63 circular.
    // Even entries in sA, odd in sB (e_{2j}=sA[j], e_{2j+1}=sB[j]), both
    // duplicated (sX[j]=sX[j+32]); indices 64/65 pad so boff+m+1 <= 65 safe.
    __shared__ float4 sA[2][66];
    __shared__ float4 sB[2][66];
    __shared__ float2 sg[2][128];
    __shared__ float4 ssum[4][32];
    __shared__ float sPG[4];          // per-warp partial of P+G (row = w>>1)
    __shared__ float s_rowmin[2];
    __shared__ int s_is_last;
    __shared__ float s_red[THREADS];

    const int tid  = threadIdx.x;
    const int w    = tid >> 5;
    const int lane = tid & 31;
    const int rl   = w >> 1;     // row within CTA (0,1)
    const int half = w & 1;      // v-half this warp covers

    // ---- stage 2 rows with 64 threads each; also reduce P+G per row ----
    {
        const int rr = tid >> 6;         // staging row
        const int i  = tid & 63;         // entry index (2 positions each)
        const float4* prow =
            reinterpret_cast<const float4*>(pred) + (blockIdx.x * 2 + rr) * 64;
        const float4* grow =
            reinterpret_cast<const float4*>(gt)   + (blockIdx.x * 2 + rr) * 64;
        float4 r = prow[i];
        float4 g = grow[i];
        const int j = i >> 1;
        if (i & 1) { sB[rr][j] = r; sB[rr][j + 32] = r; }
        else       { sA[rr][j] = r; sA[rr][j + 32] = r; }
        if (i < 4) {   // pad entries 64,65: e_{64+i} = e_i
            if (i & 1) sB[rr][64 + (i >> 1)] = r;
            else       sA[rr][64 + (i >> 1)] = r;
        }
        sg[rr][2 * i]     = make_float2(g.x, g.y);
        sg[rr][2 * i + 1] = make_float2(g.z, g.w);
        // local P+G contribution: 4 pred + 4 gt floats
        float pg = ((r.x + g.x) + (r.y + g.y)) + ((r.z + g.z) + (r.w + g.w));
        #pragma unroll
        for (int off = 16; off > 0; off >>= 1)
            pg += __shfl_xor_sync(0xffffffffu, pg, off);
        if (lane == 0) sPG[w] = pg;
    }
    __syncthreads();

    // ---- mainloop: fully unrolled 16 blocks x 4 v's, min-accumulate ----
    // Thread owns shifts 4*lane..4*lane+3; block m covers v-offsets 4m..4m+3
    // in this warp's half. Window entries A/B[boff+m], A/B[boff+m+1] hold
    // relative positions r+0..r+7 (float2 each; float4 = 2 positions).
    float ax0 = 0.f, ay0 = 0.f, ax1 = 0.f, ay1 = 0.f;
    float ax2 = 0.f, ay2 = 0.f, ax3 = 0.f, ay3 = 0.f;
    const int boff = lane + 16 * half;
    const float4* Ap = sA[rl];
    const float4* Bp = sB[rl];
    const float2* gp = sg[rl] + 64 * half;

    #pragma unroll
    for (int m = 0; m < 16; m++) {
        float2 G0 = gp[4 * m];            // gt[v0]   (broadcast)
        float2 G1 = gp[4 * m + 1];        // gt[v0+1]
        float2 G2 = gp[4 * m + 2];        // gt[v0+2]
        float2 G3 = gp[4 * m + 3];        // gt[v0+3]
        float4 Fa = Ap[boff + m];         // positions r+0 (x,y), r+1 (z,w)
        float4 Fb = Bp[boff + m];         // r+2, r+3
        float4 Fc = Ap[boff + m + 1];     // r+4, r+5 (CSE with next iter)
        float4 Fd = Bp[boff + m + 1];     // r+6, r+7 (CSE with next iter)
        // u=0: shifts 0..3 use positions r+0..r+3
        ACC(Fa, x, y, G0, ax0, ay0); ACC(Fa, z, w, G0, ax1, ay1);
        ACC(Fb, x, y, G0, ax2, ay2); ACC(Fb, z, w, G0, ax3, ay3);
        // u=1: positions r+1..r+4
        ACC(Fa, z, w, G1, ax0, ay0); ACC(Fb, x, y, G1, ax1, ay1);
        ACC(Fb, z, w, G1, ax2, ay2); ACC(Fc, x, y, G1, ax3, ay3);
        // u=2: positions r+2..r+5
        ACC(Fb, x, y, G2, ax0, ay0); ACC(Fb, z, w, G2, ax1, ay1);
        ACC(Fc, x, y, G2, ax2, ay2); ACC(Fc, z, w, G2, ax3, ay3);
        // u=3: positions r+3..r+6
        ACC(Fb, z, w, G3, ax0, ay0); ACC(Fc, x, y, G3, ax1, ay1);
        ACC(Fc, z, w, G3, ax2, ay2); ACC(Fd, x, y, G3, ax3, ay3);
    }

    // ---- per-(thread,shift) min-sum partials -> smem ----
    ssum[w][lane] = make_float4(ax0 + ay0, ax1 + ay1, ax2 + ay2, ax3 + ay3);
    __syncthreads();

    // ---- combine v-halves, MAX over shifts, rowmin = PG - 2*max ----
    if (w < 2) {
        float PG = sPG[2 * w] + sPG[2 * w + 1];
        float4 x = ssum[2 * w][lane];
        float4 y = ssum[2 * w + 1][lane];
        float t0 = x.x + y.x, t1 = x.y + y.y, t2 = x.z + y.z, t3 = x.w + y.w;
        float mx = fmaxf(fmaxf(t0, t1), fmaxf(t2, t3));
        #pragma unroll
        for (int off = 16; off > 0; off >>= 1)
            mx = fmaxf(mx, __shfl_xor_sync(0xffffffffu, mx, off));
        if (lane == 0) s_rowmin[w] = PG - 2.0f * mx;
    }
    __syncthreads();

    // ---- CTA partial + last-CTA ticket reduction ----
    if (tid == 0) {
        g_partial[blockIdx.x] = s_rowmin[0] + s_rowmin[1];
        __threadfence();
        int ticket = atomicAdd(&g_ctr, 1);
        s_is_last = (ticket == NCTA - 1);
    }
    __syncthreads();

    if (s_is_last) {
        __threadfence();
        float acc = 0.f;
        #pragma unroll
        for (int i = tid; i < NCTA; i += THREADS)
            acc += g_partial[i];
        s_red[tid] = acc;
        __syncthreads();
        #pragma unroll
        for (int off = THREADS / 2; off > 0; off >>= 1) {
            if (tid < off) s_red[tid] += s_red[tid + off];
            __syncthreads();
        }
        if (tid == 0) {
            out[0] = s_red[0] * (1.0f / ((float)NROWS * (float)V));
            g_ctr = 0;  // reset for next graph replay
        }
    }
}

extern "C" void kernel_launch(void* const* d_in, const int* in_sizes, int n_in,
                              void* d_out, int out_size)
{
    const float* pred = (const float*)d_in[0];
    const float* gt   = (const float*)d_in[1];
    polyloss_kernel<<<NCTA, THREADS>>>(pred, gt, (float*)d_out);
}

// round 12
// speedup vs baseline: 1.1285x; 1.0387x over previous
#include <cuda_runtime.h>
#include <cstdint>

// PolyLoss: N=4096 rows, V=128 circular shifts, last dim = 2.
// per_shift[n,s] = (1/V) sum_v |pred[n,(s+v)%V] - gt[n,v]|_1 ; loss = mean_n min_s
//
// Identity: |a-b| = a + b - 2*min(a,b); sum_v (p+g) = P+G is shift-invariant:
//   min_s per_shift = ( (P+G) - 2 * max_s sum_v min(p_{s+v}, g_v) ) / V.
// Inner loop per (shift,v) pair: FMNMX lo + FMNMX hi (alu pipe) + one packed
// add.rn.f32x2 accumulate (fma pipe) = 3 issue slots, 4 alu + 4 fma cycles.
//
// Shape: 2 rows per 128-thread CTA, 2 warps/row (half h covers v in
// [64h,64h+64)), lane owns shifts 4*lane..4*lane+3, fully unrolled mainloop
// with CSE'd float4 window loads and float4 gt loads.

#define NROWS 4096
#define V 128
#define NCTA 2048
#define THREADS 128

__device__ float g_partial[NCTA];
__device__ int g_ctr;

__device__ __forceinline__ uint64_t add2(uint64_t a, uint64_t b) {
    uint64_t d;
    asm("add.rn.f32x2 %0, %1, %2;" : "=l"(d) : "l"(a), "l"(b));
    return d;
}
// packed pair of mins: (min(px,gx), min(py,gy)) -> b64
__device__ __forceinline__ uint64_t minpack(float px, float py, float gx, float gy) {
    uint64_t d;
    asm("{\n\t"
        ".reg .f32 lo, hi;\n\t"
        "min.f32 lo, %1, %2;\n\t"
        "min.f32 hi, %3, %4;\n\t"
        "mov.b64 %0, {lo, hi};\n\t"
        "}" : "=l"(d) : "f"(px), "f"(gx), "f"(py), "f"(gy));
    return d;
}
__device__ __forceinline__ float lo_f(uint64_t v) { return __uint_as_float((uint32_t)v); }
__device__ __forceinline__ float hi_f(uint64_t v) { return __uint_as_float((uint32_t)(v >> 32)); }

// acc(f32x2) += (min(px,gx), min(py,gy)) : 2x FMNMX (alu) + 1x FADD2 (fma)
#define ACC(P, QX, QY, G, GX, GY, acc) \
    (acc) = add2((acc), minpack((P).QX, (P).QY, (G).GX, (G).GY))

__global__ void __launch_bounds__(THREADS, 12) polyloss_kernel(
    const float* __restrict__ pred, const float* __restrict__ gt,
    float* __restrict__ out)
{
    // Entry e_k = float4 = positions (2k, 2k+1), k=0..63 circular.
    // Even entries in sA, odd in sB (e_{2j}=sA[j], e_{2j+1}=sB[j]), both
    // duplicated (sX[j]=sX[j+32]); indices 64/65 pad so boff+m+1 <= 65 safe.
    __shared__ float4 sA[2][66];
    __shared__ float4 sB[2][66];
    __shared__ float4 sg[2][64];      // gt entries: float4 = gt[2i], gt[2i+1]
    __shared__ float4 ssum[4][32];
    __shared__ float sPG[4];          // per-warp partial of P+G (row = w>>1)
    __shared__ float s_rowmin[2];
    __shared__ int s_is_last;
    __shared__ float s_red[THREADS];

    const int tid  = threadIdx.x;
    const int w    = tid >> 5;
    const int lane = tid & 31;
    const int rl   = w >> 1;     // row within CTA (0,1)
    const int half = w & 1;      // v-half this warp covers

    // ---- stage 2 rows with 64 threads each; also reduce P+G per row ----
    {
        const int rr = tid >> 6;         // staging row
        const int i  = tid & 63;         // entry index (2 positions each)
        const float4* prow =
            reinterpret_cast<const float4*>(pred) + (blockIdx.x * 2 + rr) * 64;
        const float4* grow =
            reinterpret_cast<const float4*>(gt)   + (blockIdx.x * 2 + rr) * 64;
        float4 r = prow[i];
        float4 g = grow[i];
        const int j = i >> 1;
        if (i & 1) { sB[rr][j] = r; sB[rr][j + 32] = r; }
        else       { sA[rr][j] = r; sA[rr][j + 32] = r; }
        if (i < 4) {   // pad entries 64,65: e_{64+i} = e_i
            if (i & 1) sB[rr][64 + (i >> 1)] = r;
            else       sA[rr][64 + (i >> 1)] = r;
        }
        sg[rr][i] = g;
        // local P+G contribution: 4 pred + 4 gt floats
        float pg = ((r.x + g.x) + (r.y + g.y)) + ((r.z + g.z) + (r.w + g.w));
        #pragma unroll
        for (int off = 16; off > 0; off >>= 1)
            pg += __shfl_xor_sync(0xffffffffu, pg, off);
        if (lane == 0) sPG[w] = pg;
    }
    __syncthreads();

    // ---- mainloop: fully unrolled 16 blocks x 4 v's, packed min-accumulate --
    // Thread owns shifts 4*lane..4*lane+3; block m covers v-offsets 4m..4m+3
    // in this warp's half. Window entries A/B[boff+m], A/B[boff+m+1] hold
    // relative positions r+0..r+7 (float4 = 2 positions).
    uint64_t a0 = 0, a1 = 0, a2 = 0, a3 = 0;
    const int boff = lane + 16 * half;
    const float4* Ap = sA[rl];
    const float4* Bp = sB[rl];
    const float4* gp = sg[rl] + 32 * half;

    #pragma unroll
    for (int m = 0; m < 16; m++) {
        float4 G0 = gp[2 * m];            // gt[v0] (x,y), gt[v0+1] (z,w)
        float4 G1 = gp[2 * m + 1];        // gt[v0+2], gt[v0+3]
        float4 Fa = Ap[boff + m];         // positions r+0 (x,y), r+1 (z,w)
        float4 Fb = Bp[boff + m];         // r+2, r+3
        float4 Fc = Ap[boff + m + 1];     // r+4, r+5 (CSE with next iter)
        float4 Fd = Bp[boff + m + 1];     // r+6, r+7 (CSE with next iter)
        // u=0: shifts 0..3 use positions r+0..r+3, gt[v0]
        ACC(Fa, x, y, G0, x, y, a0); ACC(Fa, z, w, G0, x, y, a1);
        ACC(Fb, x, y, G0, x, y, a2); ACC(Fb, z, w, G0, x, y, a3);
        // u=1: positions r+1..r+4, gt[v0+1]
        ACC(Fa, z, w, G0, z, w, a0); ACC(Fb, x, y, G0, z, w, a1);
        ACC(Fb, z, w, G0, z, w, a2); ACC(Fc, x, y, G0, z, w, a3);
        // u=2: positions r+2..r+5, gt[v0+2]
        ACC(Fb, x, y, G1, x, y, a0); ACC(Fb, z, w, G1, x, y, a1);
        ACC(Fc, x, y, G1, x, y, a2); ACC(Fc, z, w, G1, x, y, a3);
        // u=3: positions r+3..r+6, gt[v0+3]
        ACC(Fb, z, w, G1, z, w, a0); ACC(Fc, x, y, G1, z, w, a1);
        ACC(Fc, z, w, G1, z, w, a2); ACC(Fd, x, y, G1, z, w, a3);
    }

    // ---- fold packed halves -> per-(thread,shift) min-sum partials ----
    float s0 = lo_f(a0) + hi_f(a0);
    float s1 = lo_f(a1) + hi_f(a1);
    float s2 = lo_f(a2) + hi_f(a2);
    float s3 = lo_f(a3) + hi_f(a3);
    ssum[w][lane] = make_float4(s0, s1, s2, s3);
    __syncthreads();

    // ---- combine v-halves, MAX over shifts, rowmin = PG - 2*max ----
    if (w < 2) {
        float PG = sPG[2 * w] + sPG[2 * w + 1];
        float4 x = ssum[2 * w][lane];
        float4 y = ssum[2 * w + 1][lane];
        float t0 = x.x + y.x, t1 = x.y + y.y, t2 = x.z + y.z, t3 = x.w + y.w;
        float mx = fmaxf(fmaxf(t0, t1), fmaxf(t2, t3));
        #pragma unroll
        for (int off = 16; off > 0; off >>= 1)
            mx = fmaxf(mx, __shfl_xor_sync(0xffffffffu, mx, off));
        if (lane == 0) s_rowmin[w] = PG - 2.0f * mx;
    }
    __syncthreads();

    // ---- CTA partial + last-CTA ticket reduction ----
    if (tid == 0) {
        g_partial[blockIdx.x] = s_rowmin[0] + s_rowmin[1];
        __threadfence();
        int ticket = atomicAdd(&g_ctr, 1);
        s_is_last = (ticket == NCTA - 1);
    }
    __syncthreads();

    if (s_is_last) {
        __threadfence();
        float acc = 0.f;
        #pragma unroll
        for (int i = tid; i < NCTA; i += THREADS)
            acc += g_partial[i];
        s_red[tid] = acc;
        __syncthreads();
        #pragma unroll
        for (int off = THREADS / 2; off > 0; off >>= 1) {
            if (tid < off) s_red[tid] += s_red[tid + off];
            __syncthreads();
        }
        if (tid == 0) {
            out[0] = s_red[0] * (1.0f / ((float)NROWS * (float)V));
            g_ctr = 0;  // reset for next graph replay
        }
    }
}

extern "C" void kernel_launch(void* const* d_in, const int* in_sizes, int n_in,
                              void* d_out, int out_size)
{
    const float* pred = (const float*)d_in[0];
    const float* gt   = (const float*)d_in[1];
    polyloss_kernel<<<NCTA, THREADS>>>(pred, gt, (float*)d_out);
}

// round 13
// speedup vs baseline: 1.4276x; 1.2650x over previous
#include <cuda_runtime.h>
#include <cuda_fp16.h>
#include <cstdint>

// PolyLoss: N=4096 rows, V=128 circular shifts, last dim = 2.
// per_shift[n,s] = (1/V) sum_v |pred[n,(s+v)%V] - gt[n,v]|_1 ; loss = mean_n min_s
//
// Identity: |a-b| = a + b - 2*min(a,b); sum_v (p+g) = P+G is shift-invariant:
//   min_s per_shift = ( (P+G) - 2 * max_s sum_v min(p_{s+v}, g_v) ) / V.
// fp16x2 inner loop: one position's 2 components = one 32-bit reg. Per
// (shift,v) pair: min.f16x2 (alu) + add.rn.f16x2 (fma) = 2 slots, 2+2 cyc.
// fp16 accumulators fold to fp32 every 16 v (chain <= 16 adds; rounding RMS
// ~3e-4 rel per row, threshold 1e-3). P+G computed in fp32 at staging.
//
// Shape: 2 rows per 128-thread CTA, 2 warps/row (half h covers v in
// [64h,64h+64)), lane owns shifts 4*lane..4*lane+3, fully unrolled.

#define NROWS 4096
#define V 128
#define NCTA 2048
#define THREADS 128

__device__ float g_partial[NCTA];
__device__ int g_ctr;

__device__ __forceinline__ uint32_t hmin2(uint32_t a, uint32_t b) {
    uint32_t d;
    asm("min.f16x2 %0, %1, %2;" : "=r"(d) : "r"(a), "r"(b));
    return d;
}
__device__ __forceinline__ uint32_t hadd2(uint32_t a, uint32_t b) {
    uint32_t d;
    asm("add.rn.f16x2 %0, %1, %2;" : "=r"(d) : "r"(a), "r"(b));
    return d;
}
__device__ __forceinline__ float2 h2f(uint32_t h) {
    __half2 hv = *reinterpret_cast<__half2*>(&h);
    return __half22float2(hv);
}
__device__ __forceinline__ uint32_t pack_h2(float x, float y) {
    __half2 hv = __float22half2_rn(make_float2(x, y));
    return *reinterpret_cast<uint32_t*>(&hv);
}

// acc(f16x2) += min(p, g): 1x HMNMX2 (alu) + 1x HADD2 (fma)
#define ACC(acc, P, G) (acc) = hadd2((acc), hmin2((P), (G)))

__global__ void __launch_bounds__(THREADS, 12) polyloss_kernel(
    const float* __restrict__ pred, const float* __restrict__ gt,
    float* __restrict__ out)
{
    // sp[k] = fp16x2 of position k's 2 components; k=0..255 (circular dup).
    // sg[k] = gt position k, k=0..127. uint4-aligned for LDS.128.
    __shared__ __align__(16) uint32_t sp[2][256];
    __shared__ __align__(16) uint32_t sg[2][128];
    __shared__ float4 ssum[4][32];
    __shared__ float sPG[4];
    __shared__ float s_rowmin[2];
    __shared__ int s_is_last;
    __shared__ float s_red[THREADS];

    const int tid  = threadIdx.x;
    const int w    = tid >> 5;
    const int lane = tid & 31;
    const int rl   = w >> 1;     // row within CTA (0,1)
    const int half = w & 1;      // v-half this warp covers

    // ---- stage 2 rows, 64 threads each: i<32 -> pred uint4 i (positions
    //      4i..4i+3), i>=32 -> gt uint4 i-32. fp32 P+G reduced per warp. ----
    {
        const int rr = tid >> 6;
        const int i  = tid & 63;
        const int rowg = blockIdx.x * 2 + rr;
        float4 v0, v1;
        if (i < 32) {
            const float4* prow = reinterpret_cast<const float4*>(pred) + rowg * 64;
            v0 = prow[2 * i];
            v1 = prow[2 * i + 1];
        } else {
            const float4* grow = reinterpret_cast<const float4*>(gt) + rowg * 64;
            v0 = grow[2 * (i - 32)];
            v1 = grow[2 * (i - 32) + 1];
        }
        uint4 packed = make_uint4(pack_h2(v0.x, v0.y), pack_h2(v0.z, v0.w),
                                  pack_h2(v1.x, v1.y), pack_h2(v1.z, v1.w));
        if (i < 32) {
            *reinterpret_cast<uint4*>(&sp[rr][4 * i])       = packed;
            *reinterpret_cast<uint4*>(&sp[rr][4 * i + 128]) = packed;  // dup
        } else {
            *reinterpret_cast<uint4*>(&sg[rr][4 * (i - 32)]) = packed;
        }
        // fp32 P+G: each float counted exactly once across the 64 threads
        float pg = ((v0.x + v0.y) + (v0.z + v0.w)) + ((v1.x + v1.y) + (v1.z + v1.w));
        #pragma unroll
        for (int off = 16; off > 0; off >>= 1)
            pg += __shfl_xor_sync(0xffffffffu, pg, off);
        if (lane == 0) sPG[w] = pg;
    }
    __syncthreads();

    // ---- mainloop: 16 blocks x 4 v's. Window = 8 consecutive positions
    //      starting at 4*(lane+16*half+m); one new LDS.128 + one G LDS.128
    //      per block. Fold fp16 accs to fp32 every 4 blocks (16 adds max). ----
    uint32_t a0 = 0, a1 = 0, a2 = 0, a3 = 0;     // fp16x2 accumulators
    float m0x = 0.f, m0y = 0.f, m1x = 0.f, m1y = 0.f;
    float m2x = 0.f, m2y = 0.f, m3x = 0.f, m3y = 0.f;
    const uint4* wp = reinterpret_cast<const uint4*>(&sp[rl][0]) + lane + 16 * half;
    const uint4* gp = reinterpret_cast<const uint4*>(&sg[rl][0]) + 16 * half;

    uint4 W0 = wp[0];
    #pragma unroll
    for (int m = 0; m < 16; m++) {
        uint4 G  = gp[m];        // gt[v0..v0+3], broadcast
        uint4 W1 = wp[m + 1];    // next 4 positions (CSE: next iter's W0)
        // u=0: positions +0..+3
        ACC(a0, W0.x, G.x); ACC(a1, W0.y, G.x); ACC(a2, W0.z, G.x); ACC(a3, W0.w, G.x);
        // u=1: positions +1..+4
        ACC(a0, W0.y, G.y); ACC(a1, W0.z, G.y); ACC(a2, W0.w, G.y); ACC(a3, W1.x, G.y);
        // u=2: positions +2..+5
        ACC(a0, W0.z, G.z); ACC(a1, W0.w, G.z); ACC(a2, W1.x, G.z); ACC(a3, W1.y, G.z);
        // u=3: positions +3..+6
        ACC(a0, W0.w, G.w); ACC(a1, W1.x, G.w); ACC(a2, W1.y, G.w); ACC(a3, W1.z, G.w);
        W0 = W1;
        if ((m & 3) == 3) {   // fold to fp32, reset fp16 accumulators
            float2 f;
            f = h2f(a0); m0x += f.x; m0y += f.y; a0 = 0;
            f = h2f(a1); m1x += f.x; m1y += f.y; a1 = 0;
            f = h2f(a2); m2x += f.x; m2y += f.y; a2 = 0;
            f = h2f(a3); m3x += f.x; m3y += f.y; a3 = 0;
        }
    }

    // ---- per-(thread,shift) min-sum partials -> smem ----
    ssum[w][lane] = make_float4(m0x + m0y, m1x + m1y, m2x + m2y, m3x + m3y);
    __syncthreads();

    // ---- combine v-halves, MAX over shifts, rowmin = PG - 2*max ----
    if (w < 2) {
        float PG = sPG[2 * w] + sPG[2 * w + 1];
        float4 x = ssum[2 * w][lane];
        float4 y = ssum[2 * w + 1][lane];
        float t0 = x.x + y.x, t1 = x.y + y.y, t2 = x.z + y.z, t3 = x.w + y.w;
        float mx = fmaxf(fmaxf(t0, t1), fmaxf(t2, t3));
        #pragma unroll
        for (int off = 16; off > 0; off >>= 1)
            mx = fmaxf(mx, __shfl_xor_sync(0xffffffffu, mx, off));
        if (lane == 0) s_rowmin[w] = PG - 2.0f * mx;
    }
    __syncthreads();

    // ---- CTA partial + last-CTA ticket reduction ----
    if (tid == 0) {
        g_partial[blockIdx.x] = s_rowmin[0] + s_rowmin[1];
        __threadfence();
        int ticket = atomicAdd(&g_ctr, 1);
        s_is_last = (ticket == NCTA - 1);
    }
    __syncthreads();

    if (s_is_last) {
        __threadfence();
        float acc = 0.f;
        #pragma unroll
        for (int i = tid; i < NCTA; i += THREADS)
            acc += g_partial[i];
        s_red[tid] = acc;
        __syncthreads();
        #pragma unroll
        for (int off = THREADS / 2; off > 0; off >>= 1) {
            if (tid < off) s_red[tid] += s_red[tid + off];
            __syncthreads();
        }
        if (tid == 0) {
            out[0] = s_red[0] * (1.0f / ((float)NROWS * (float)V));
            g_ctr = 0;  // reset for next graph replay
        }
    }
}

extern "C" void kernel_launch(void* const* d_in, const int* in_sizes, int n_in,
                              void* d_out, int out_size)
{
    const float* pred = (const float*)d_in[0];
    const float* gt   = (const float*)d_in[1];
    polyloss_kernel<<<NCTA, THREADS>>>(pred, gt, (float*)d_out);
}